// round 1
// baseline (speedup 1.0000x reference)
#include <cuda_runtime.h>
#include <math.h>

#define NATOMS 8192
#define APM 32
#define NMOL 256
#define F 100
#define NG 25
#define KNN 28
#define NL 4
#define TBL 4096
#define CUTF 6.0f
#define NCH ((TBL + 1 + 31) / 32)   // 129 t-chunks of 32

// ---------------- device scratch (static, no allocations) ----------------
__device__ float g_table[NL][TBL + 1][F];   // per-layer filter table Wf(d)
__device__ float g_h[NATOMS * F];
__device__ float g_agg[NATOMS * F];
__device__ int g_ecnt[NATOMS];
__device__ unsigned char g_ej[NATOMS][KNN]; // local (in-molecule) neighbor index
__device__ float g_et[NATOMS][KNN];         // d * TBL/CUT (table coordinate)
__device__ float g_ec[NATOMS][KNN];         // cosine cutoff weight

__device__ __forceinline__ float sspf(float x) {
    // softplus(x) - log(2), numerically stable
    float sp = (x > 0.f) ? (x + log1pf(expf(-x))) : log1pf(expf(x));
    return sp - 0.69314718055994531f;
}

// ---------------- KNN within each 32-atom molecule ----------------
__global__ void knn_kernel(const float* __restrict__ pos) {
    int mol = blockIdx.x;
    int a = threadIdx.x;
    int gi = mol * APM + a;
    __shared__ float px[APM], py[APM], pz[APM];
    px[a] = pos[gi * 3 + 0];
    py[a] = pos[gi * 3 + 1];
    pz[a] = pos[gi * 3 + 2];
    __syncthreads();
    float d[APM];
    float ax = px[a], ay = py[a], az = pz[a];
    for (int j = 0; j < APM; j++) {
        float dx = ax - px[j], dy = ay - py[j], dz = az - pz[j];
        float d2 = dx * dx + dy * dy + dz * dz;
        d[j] = (j == a || d2 > CUTF * CUTF) ? 1e30f : sqrtf(d2);
    }
    int cnt = 0;
    for (int s = 0; s < KNN; s++) {
        float best = 1e29f;
        int bj = -1;
        for (int j = 0; j < APM; j++)
            if (d[j] < best) { best = d[j]; bj = j; }
        if (bj < 0) break;
        g_ej[gi][s] = (unsigned char)bj;
        g_et[gi][s] = best * ((float)TBL / CUTF);
        g_ec[gi][s] = 0.5f * (cosf(best * (3.14159265358979323846f / CUTF)) + 1.0f);
        d[bj] = 1e30f;
        cnt++;
    }
    g_ecnt[gi] = cnt;
}

// ---------------- embedding gather ----------------
__global__ void embed_kernel(const int* __restrict__ z, const float* __restrict__ emb) {
    int i = blockIdx.x * blockDim.x + threadIdx.x;
    if (i < NATOMS * F) {
        int a = i / F, f = i % F;
        g_h[i] = emb[z[a] * F + f];
    }
}

// ---------------- build filter table: Wf_l(d) for d on a TBL grid ----------------
// grid = NL*NCH blocks, 256 threads. Each block: one layer, 32 grid points.
__global__ void table_kernel(const float* __restrict__ mlp_w1, const float* __restrict__ mlp_b1,
                             const float* __restrict__ mlp_w2, const float* __restrict__ mlp_b2) {
    extern __shared__ float sm[];
    float* w1 = sm;                 // NG*F   = 2500
    float* w2 = w1 + NG * F;        // F*F    = 10000
    float* shid = w2 + F * F;       // 32*F   = 3200
    float* sea = shid + APM * F;    // 32*NG  = 800
    float* b1 = sea + APM * NG;     // F
    float* b2 = b1 + F;             // F

    int l = blockIdx.x / NCH;
    int c = blockIdx.x % NCH;
    int tid = threadIdx.x;

    for (int i = tid; i < NG * F; i += blockDim.x) w1[i] = mlp_w1[l * NG * F + i];
    for (int i = tid; i < F * F; i += blockDim.x) w2[i] = mlp_w2[l * F * F + i];
    if (tid < F) { b1[tid] = mlp_b1[l * F + tid]; b2[tid] = mlp_b2[l * F + tid]; }
    __syncthreads();

    // Phase A: gaussian features for 32 grid points
    for (int idx = tid; idx < APM * NG; idx += blockDim.x) {
        int tl = idx / NG, g = idx % NG;
        int t = c * 32 + tl;
        float dd = (float)t * (CUTF / (float)TBL);
        float u = dd - 0.25f * (float)g;
        sea[idx] = expf(-8.0f * u * u);
    }
    __syncthreads();

    // Phase B: hid = ssp(ea @ W1 + b1)   [32 x 100]; 4x4 register tile, 200 threads
    if (tid < 200) {
        int ta = tid / 25, fa = tid % 25;
        float acc[4][4];
#pragma unroll
        for (int r = 0; r < 4; r++)
#pragma unroll
            for (int q = 0; q < 4; q++) acc[r][q] = b1[fa * 4 + q];
#pragma unroll
        for (int k = 0; k < NG; k++) {
            float4 wv = *(const float4*)&w1[k * F + fa * 4];
#pragma unroll
            for (int r = 0; r < 4; r++) {
                float av = sea[(ta * 4 + r) * NG + k];
                acc[r][0] += av * wv.x; acc[r][1] += av * wv.y;
                acc[r][2] += av * wv.z; acc[r][3] += av * wv.w;
            }
        }
#pragma unroll
        for (int r = 0; r < 4; r++)
#pragma unroll
            for (int q = 0; q < 4; q++)
                shid[(ta * 4 + r) * F + fa * 4 + q] = sspf(acc[r][q]);
    }
    __syncthreads();

    // Phase C: Wf = hid @ W2 + b2 -> g_table
    if (tid < 200) {
        int ta = tid / 25, fa = tid % 25;
        float acc[4][4];
#pragma unroll
        for (int r = 0; r < 4; r++)
#pragma unroll
            for (int q = 0; q < 4; q++) acc[r][q] = b2[fa * 4 + q];
#pragma unroll 4
        for (int k = 0; k < F; k++) {
            float4 wv = *(const float4*)&w2[k * F + fa * 4];
#pragma unroll
            for (int r = 0; r < 4; r++) {
                float av = shid[(ta * 4 + r) * F + k];
                acc[r][0] += av * wv.x; acc[r][1] += av * wv.y;
                acc[r][2] += av * wv.z; acc[r][3] += av * wv.w;
            }
        }
#pragma unroll
        for (int r = 0; r < 4; r++) {
            int t = c * 32 + ta * 4 + r;
            if (t <= TBL) {
#pragma unroll
                for (int q = 0; q < 4; q++)
                    g_table[l][t][fa * 4 + q] = acc[r][q];
            }
        }
    }
}

// ---------------- per-molecule CFConv gather: x1 = h@lin1; agg = sum_e x1[j]*Wf(d)*ccut --------
__global__ void agg_kernel(const float* __restrict__ lin1_w, int l) {
    extern __shared__ float sm[];
    float* w1 = sm;                   // F*F
    float* hm = w1 + F * F;           // APM*F
    float* x1 = hm + APM * F;         // APM*F
    float* set = x1 + APM * F;        // APM*KNN
    float* sec = set + APM * KNN;     // APM*KNN
    int* scnt = (int*)(sec + APM * KNN);                  // APM
    unsigned char* sej = (unsigned char*)(scnt + APM);    // APM*KNN

    int mol = blockIdx.x, tid = threadIdx.x;
    int base = mol * APM;

    for (int i = tid; i < F * F; i += blockDim.x) w1[i] = lin1_w[l * F * F + i];
    for (int i = tid; i < APM * F; i += blockDim.x) hm[i] = g_h[base * F + i];
    for (int i = tid; i < APM * KNN; i += blockDim.x) {
        int a = i / KNN, s = i % KNN;
        set[i] = g_et[base + a][s];
        sec[i] = g_ec[base + a][s];
        sej[i] = g_ej[base + a][s];
    }
    if (tid < APM) scnt[tid] = g_ecnt[base + tid];
    __syncthreads();

    // x1 = hm @ w1  (32x100 @ 100x100), 4x4 tile
    if (tid < 200) {
        int ta = tid / 25, fa = tid % 25;
        float acc[4][4];
#pragma unroll
        for (int r = 0; r < 4; r++)
#pragma unroll
            for (int q = 0; q < 4; q++) acc[r][q] = 0.f;
#pragma unroll 4
        for (int k = 0; k < F; k++) {
            float4 wv = *(const float4*)&w1[k * F + fa * 4];
#pragma unroll
            for (int r = 0; r < 4; r++) {
                float av = hm[(ta * 4 + r) * F + k];
                acc[r][0] += av * wv.x; acc[r][1] += av * wv.y;
                acc[r][2] += av * wv.z; acc[r][3] += av * wv.w;
            }
        }
#pragma unroll
        for (int r = 0; r < 4; r++)
#pragma unroll
            for (int q = 0; q < 4; q++)
                x1[(ta * 4 + r) * F + fa * 4 + q] = acc[r][q];
    }
    __syncthreads();

    // aggregation: 2 atom-groups x 100 features
    const float* tb = &g_table[l][0][0];
    int grp = tid >> 7;         // 0 or 1
    int fid = tid & 127;
    if (fid < F) {
        for (int a = grp; a < APM; a += 2) {
            int cnt = scnt[a];
            float acc = 0.f;
            for (int s = 0; s < cnt; s++) {
                int e = a * KNN + s;
                float tpos = set[e];
                int t0 = min((int)tpos, TBL - 1);
                float fr = tpos - (float)t0;
                const float* row = tb + t0 * F + fid;
                float w = row[0] + fr * (row[F] - row[0]);
                acc += x1[(int)sej[e] * F + fid] * w * sec[e];
            }
            g_agg[(base + a) * F + fid] = acc;
        }
    }
}

// ---------------- per-molecule node update: h += ssp(agg@lin2+b2)@lin_w + lin_b ----------
__global__ void update_kernel(const float* __restrict__ lin2_w, const float* __restrict__ lin2_b,
                              const float* __restrict__ lin_w, const float* __restrict__ lin_b, int l) {
    extern __shared__ float sm[];
    float* w2 = sm;               // F*F
    float* ww = w2 + F * F;       // F*F
    float* aggs = ww + F * F;     // APM*F
    float* ts = aggs + APM * F;   // APM*F
    float* b2 = ts + APM * F;     // F
    float* bb = b2 + F;           // F

    int mol = blockIdx.x, tid = threadIdx.x;
    int base = mol * APM;

    for (int i = tid; i < F * F; i += blockDim.x) {
        w2[i] = lin2_w[l * F * F + i];
        ww[i] = lin_w[l * F * F + i];
    }
    for (int i = tid; i < APM * F; i += blockDim.x) aggs[i] = g_agg[base * F + i];
    if (tid < F) { b2[tid] = lin2_b[l * F + tid]; bb[tid] = lin_b[l * F + tid]; }
    __syncthreads();

    if (tid < 200) {
        int ta = tid / 25, fa = tid % 25;
        float acc[4][4];
#pragma unroll
        for (int r = 0; r < 4; r++)
#pragma unroll
            for (int q = 0; q < 4; q++) acc[r][q] = b2[fa * 4 + q];
#pragma unroll 4
        for (int k = 0; k < F; k++) {
            float4 wv = *(const float4*)&w2[k * F + fa * 4];
#pragma unroll
            for (int r = 0; r < 4; r++) {
                float av = aggs[(ta * 4 + r) * F + k];
                acc[r][0] += av * wv.x; acc[r][1] += av * wv.y;
                acc[r][2] += av * wv.z; acc[r][3] += av * wv.w;
            }
        }
#pragma unroll
        for (int r = 0; r < 4; r++)
#pragma unroll
            for (int q = 0; q < 4; q++)
                ts[(ta * 4 + r) * F + fa * 4 + q] = sspf(acc[r][q]);
    }
    __syncthreads();

    if (tid < 200) {
        int ta = tid / 25, fa = tid % 25;
        float acc[4][4];
#pragma unroll
        for (int r = 0; r < 4; r++)
#pragma unroll
            for (int q = 0; q < 4; q++) acc[r][q] = bb[fa * 4 + q];
#pragma unroll 4
        for (int k = 0; k < F; k++) {
            float4 wv = *(const float4*)&ww[k * F + fa * 4];
#pragma unroll
            for (int r = 0; r < 4; r++) {
                float av = ts[(ta * 4 + r) * F + k];
                acc[r][0] += av * wv.x; acc[r][1] += av * wv.y;
                acc[r][2] += av * wv.z; acc[r][3] += av * wv.w;
            }
        }
#pragma unroll
        for (int r = 0; r < 4; r++)
#pragma unroll
            for (int q = 0; q < 4; q++)
                g_h[base * F + (ta * 4 + r) * F + fa * 4 + q] += acc[r][q];
    }
}

// ---------------- readout head + per-molecule reduction ----------------
#define HOUT 50
__global__ void readout_kernel(const float* __restrict__ w1, const float* __restrict__ b1,
                               const float* __restrict__ w2, const float* __restrict__ b2,
                               float* __restrict__ out) {
    __shared__ float sw1[F * HOUT];       // 5000
    __shared__ float sh[APM * 101];       // padded stride 101 (conflict-free)
    __shared__ float sw2[HOUT];
    __shared__ float sb1[HOUT];
    __shared__ float ered[4][APM];

    int mol = blockIdx.x, tid = threadIdx.x;  // 128 threads
    int base = mol * APM;

    for (int i = tid; i < F * HOUT; i += blockDim.x) sw1[i] = w1[i];
    for (int i = tid; i < APM * F; i += blockDim.x) {
        int a = i / F, k = i % F;
        sh[a * 101 + k] = g_h[base * F + i];
    }
    if (tid < HOUT) { sw2[tid] = w2[tid]; sb1[tid] = b1[tid]; }
    __syncthreads();

    int a = tid & 31;
    int q = tid >> 5;  // 0..3
    float e = 0.f;
    for (int j = q; j < HOUT; j += 4) {
        float acc = sb1[j];
#pragma unroll 4
        for (int k = 0; k < F; k++) acc += sh[a * 101 + k] * sw1[k * HOUT + j];
        e += sspf(acc) * sw2[j];
    }
    ered[q][a] = e;
    __syncthreads();
    if (tid < APM) {
        float tot = b2[0] + ered[0][tid] + ered[1][tid] + ered[2][tid] + ered[3][tid];
        // warp reduce over 32 atoms
        for (int off = 16; off > 0; off >>= 1)
            tot += __shfl_down_sync(0xffffffffu, tot, off);
        if (tid == 0) out[mol] = tot;
    }
}

// ---------------- launch ----------------
extern "C" void kernel_launch(void* const* d_in, const int* in_sizes, int n_in,
                              void* d_out, int out_size) {
    const int* z        = (const int*)d_in[0];
    const float* pos    = (const float*)d_in[1];
    // d_in[2] = ptr (molecules are fixed 32-atom blocks)
    const float* emb    = (const float*)d_in[3];
    const float* mlp_w1 = (const float*)d_in[4];
    const float* mlp_b1 = (const float*)d_in[5];
    const float* mlp_w2 = (const float*)d_in[6];
    const float* mlp_b2 = (const float*)d_in[7];
    const float* lin1_w = (const float*)d_in[8];
    const float* lin2_w = (const float*)d_in[9];
    const float* lin2_b = (const float*)d_in[10];
    const float* lin_w  = (const float*)d_in[11];
    const float* lin_b  = (const float*)d_in[12];
    const float* out_w1 = (const float*)d_in[13];
    const float* out_b1 = (const float*)d_in[14];
    const float* out_w2 = (const float*)d_in[15];
    const float* out_b2 = (const float*)d_in[16];
    float* out = (float*)d_out;

    const int TBL_SMEM = (NG * F + F * F + APM * F + APM * NG + 2 * F) * 4;            // 66800
    const int AGG_SMEM = (F * F + 2 * APM * F + 2 * APM * KNN) * 4 + APM * 4 + APM * KNN; // 73792
    const int UPD_SMEM = (2 * F * F + 2 * APM * F + 2 * F) * 4;                         // 106400

    cudaFuncSetAttribute(table_kernel, cudaFuncAttributeMaxDynamicSharedMemorySize, TBL_SMEM);
    cudaFuncSetAttribute(agg_kernel, cudaFuncAttributeMaxDynamicSharedMemorySize, AGG_SMEM);
    cudaFuncSetAttribute(update_kernel, cudaFuncAttributeMaxDynamicSharedMemorySize, UPD_SMEM);

    knn_kernel<<<NMOL, APM>>>(pos);
    table_kernel<<<NL * NCH, 256, TBL_SMEM>>>(mlp_w1, mlp_b1, mlp_w2, mlp_b2);
    embed_kernel<<<(NATOMS * F + 255) / 256, 256>>>(z, emb);
    for (int l = 0; l < NL; l++) {
        agg_kernel<<<NMOL, 256, AGG_SMEM>>>(lin1_w, l);
        update_kernel<<<NMOL, 256, UPD_SMEM>>>(lin2_w, lin2_b, lin_w, lin_b, l);
    }
    readout_kernel<<<NMOL, 128>>>(out_w1, out_b1, out_w2, out_b2, out);
}

// round 3
// speedup vs baseline: 1.2635x; 1.2635x over previous
#include <cuda_runtime.h>
#include <math.h>

#define NATOMS 8192
#define APM 32
#define NMOL 256
#define F 100
#define NG 25
#define KNN 28
#define NL 4
#define TBL 4096
#define CUTF 6.0f
#define NCH ((TBL + 1 + 31) / 32)   // 129 t-chunks of 32

// ---------------- device scratch (static, no allocations) ----------------
__device__ float  g_table[NL][TBL + 1][F];   // plain filter table
__device__ float2 g_tab2[NL][TBL + 1][F];    // (value, delta-to-next) interleaved
__device__ unsigned char g_ej[NATOMS][KNN];  // local neighbor index (padded: 0)
__device__ float g_et[NATOMS][KNN];          // d * TBL/CUT (padded: 0)
__device__ float g_ec[NATOMS][KNN];          // cosine cutoff (padded: 0 -> no contribution)

__device__ __forceinline__ float sspf(float x) {
    float sp = (x > 0.f) ? (x + log1pf(expf(-x))) : log1pf(expf(x));
    return sp - 0.69314718055994531f;
}

// ---------------- KNN within each 32-atom molecule (padded to KNN) ----------------
__global__ void knn_kernel(const float* __restrict__ pos) {
    int mol = blockIdx.x;
    int a = threadIdx.x;
    int gi = mol * APM + a;
    __shared__ float px[APM], py[APM], pz[APM];
    px[a] = pos[gi * 3 + 0];
    py[a] = pos[gi * 3 + 1];
    pz[a] = pos[gi * 3 + 2];
    __syncthreads();
    float d[APM];
    float ax = px[a], ay = py[a], az = pz[a];
    for (int j = 0; j < APM; j++) {
        float dx = ax - px[j], dy = ay - py[j], dz = az - pz[j];
        float d2 = dx * dx + dy * dy + dz * dz;
        d[j] = (j == a || d2 > CUTF * CUTF) ? 1e30f : sqrtf(d2);
    }
    for (int s = 0; s < KNN; s++) {
        float best = 1e29f;
        int bj = -1;
        for (int j = 0; j < APM; j++)
            if (d[j] < best) { best = d[j]; bj = j; }
        if (bj >= 0) {
            g_ej[gi][s] = (unsigned char)bj;
            g_et[gi][s] = best * ((float)TBL / CUTF);
            g_ec[gi][s] = 0.5f * (cosf(best * (3.14159265358979323846f / CUTF)) + 1.0f);
            d[bj] = 1e30f;
        } else {
            g_ej[gi][s] = 0;
            g_et[gi][s] = 0.f;
            g_ec[gi][s] = 0.f;   // zero weight -> contributes nothing
        }
    }
}

// ---------------- build filter table: Wf_l(d) on TBL grid ----------------
__global__ void table_kernel(const float* __restrict__ mlp_w1, const float* __restrict__ mlp_b1,
                             const float* __restrict__ mlp_w2, const float* __restrict__ mlp_b2) {
    extern __shared__ float sm[];
    float* w1 = sm;                 // NG*F
    float* w2 = w1 + NG * F;        // F*F
    float* shid = w2 + F * F;       // 32*F
    float* sea = shid + APM * F;    // 32*NG
    float* b1 = sea + APM * NG;     // F
    float* b2 = b1 + F;             // F

    int l = blockIdx.x / NCH;
    int c = blockIdx.x % NCH;
    int tid = threadIdx.x;

    for (int i = tid; i < NG * F; i += blockDim.x) w1[i] = mlp_w1[l * NG * F + i];
    for (int i = tid; i < F * F; i += blockDim.x) w2[i] = mlp_w2[l * F * F + i];
    if (tid < F) { b1[tid] = mlp_b1[l * F + tid]; b2[tid] = mlp_b2[l * F + tid]; }
    __syncthreads();

    for (int idx = tid; idx < APM * NG; idx += blockDim.x) {
        int tl = idx / NG, g = idx % NG;
        int t = c * 32 + tl;
        float dd = (float)t * (CUTF / (float)TBL);
        float u = dd - 0.25f * (float)g;
        sea[idx] = expf(-8.0f * u * u);
    }
    __syncthreads();

    if (tid < 200) {
        int ta = tid / 25, fa = tid % 25;
        float acc[4][4];
#pragma unroll
        for (int r = 0; r < 4; r++)
#pragma unroll
            for (int q = 0; q < 4; q++) acc[r][q] = b1[fa * 4 + q];
#pragma unroll
        for (int k = 0; k < NG; k++) {
            float4 wv = *(const float4*)&w1[k * F + fa * 4];
#pragma unroll
            for (int r = 0; r < 4; r++) {
                float av = sea[(ta * 4 + r) * NG + k];
                acc[r][0] += av * wv.x; acc[r][1] += av * wv.y;
                acc[r][2] += av * wv.z; acc[r][3] += av * wv.w;
            }
        }
#pragma unroll
        for (int r = 0; r < 4; r++)
#pragma unroll
            for (int q = 0; q < 4; q++)
                shid[(ta * 4 + r) * F + fa * 4 + q] = sspf(acc[r][q]);
    }
    __syncthreads();

    if (tid < 200) {
        int ta = tid / 25, fa = tid % 25;
        float acc[4][4];
#pragma unroll
        for (int r = 0; r < 4; r++)
#pragma unroll
            for (int q = 0; q < 4; q++) acc[r][q] = b2[fa * 4 + q];
#pragma unroll 4
        for (int k = 0; k < F; k++) {
            float4 wv = *(const float4*)&w2[k * F + fa * 4];
#pragma unroll
            for (int r = 0; r < 4; r++) {
                float av = shid[(ta * 4 + r) * F + k];
                acc[r][0] += av * wv.x; acc[r][1] += av * wv.y;
                acc[r][2] += av * wv.z; acc[r][3] += av * wv.w;
            }
        }
#pragma unroll
        for (int r = 0; r < 4; r++) {
            int t = c * 32 + ta * 4 + r;
            if (t <= TBL) {
#pragma unroll
                for (int q = 0; q < 4; q++)
                    g_table[l][t][fa * 4 + q] = acc[r][q];
            }
        }
    }
}

// ---------------- convert plain table -> interleaved (v, dv) ----------------
__global__ void tab2_kernel() {
    const int PER_L = (TBL + 1) * F;
    int idx = blockIdx.x * blockDim.x + threadIdx.x;
    if (idx >= NL * PER_L) return;
    int l = idx / PER_L;
    int j = idx - l * PER_L;
    int t = j / F;
    const float* base = &g_table[0][0][0];
    float v = base[idx];
    float nv = (t < TBL) ? base[idx + F] : v;
    float2* out = &g_tab2[0][0][0];
    out[idx] = make_float2(v, nv - v);
}

// ---------------- fused per-molecule network kernel ----------------
// smem layout (floats unless noted)
#define OFF_W 0          // 10000 (weight staging, also out_w1 5000)
#define OFF_H 10000      // 3200
#define OFF_X 13200      // 3200
#define OFF_A 16400      // 3200
#define OFF_EPK 19600    // float2[896] = 1792 floats  (fr, ccut)
#define OFF_EI 21392     // int[896]
#define OFF_B2 22288     // 400  lin2_b all layers
#define OFF_BB 22688     // 400  lin_b all layers
#define OFF_OB1 23088    // 64   out_b1
#define OFF_OW2 23152    // 64   out_w2
#define OFF_ERED 23216   // 256
#define OFF_EJ 23472     // 896 bytes = 224 floats
#define MOL_SMEM_FLOATS (23472 + 224)
#define MOL_SMEM_BYTES (MOL_SMEM_FLOATS * 4)

__device__ __forceinline__ void cp_async16(float* smem_dst, const float* gsrc) {
    unsigned sa = (unsigned)__cvta_generic_to_shared(smem_dst);
    asm volatile("cp.async.ca.shared.global [%0], [%1], 16;" :: "r"(sa), "l"(gsrc));
}

__device__ __forceinline__ void copy_w_sync(float* dst, const float* __restrict__ src,
                                            int n, int tid) {
    for (int i = tid * 4; i < n; i += 1024)
        *(float4*)(dst + i) = *(const float4*)(src + i);
}

// modes: 0 = C = A@W ; 1 = C = ssp(A@W + bias) ; 2 = C += A@W + bias
__device__ __forceinline__ void gemm_tile(const float* __restrict__ A,
                                          const float* __restrict__ W,
                                          float* __restrict__ C,
                                          const float* __restrict__ bias,
                                          int mode, int tid) {
    if (tid >= 200) return;
    int ta = tid / 25, fa = tid - (tid / 25) * 25;
    float acc[4][4];
#pragma unroll
    for (int r = 0; r < 4; r++)
#pragma unroll
        for (int q = 0; q < 4; q++) acc[r][q] = (mode == 0) ? 0.f : bias[fa * 4 + q];
#pragma unroll 4
    for (int k = 0; k < F; k++) {
        float4 wv = *(const float4*)&W[k * F + fa * 4];
#pragma unroll
        for (int r = 0; r < 4; r++) {
            float av = A[(ta * 4 + r) * F + k];
            acc[r][0] = fmaf(av, wv.x, acc[r][0]);
            acc[r][1] = fmaf(av, wv.y, acc[r][1]);
            acc[r][2] = fmaf(av, wv.z, acc[r][2]);
            acc[r][3] = fmaf(av, wv.w, acc[r][3]);
        }
    }
#pragma unroll
    for (int r = 0; r < 4; r++) {
        float* crow = &C[(ta * 4 + r) * F + fa * 4];
#pragma unroll
        for (int q = 0; q < 4; q++) {
            if (mode == 0) crow[q] = acc[r][q];
            else if (mode == 1) crow[q] = sspf(acc[r][q]);
            else crow[q] += acc[r][q];
        }
    }
}

__global__ __launch_bounds__(256) void mol_kernel(
    const int* __restrict__ z, const float* __restrict__ emb,
    const float* __restrict__ lin1_w, const float* __restrict__ lin2_w,
    const float* __restrict__ lin2_b, const float* __restrict__ lin_w,
    const float* __restrict__ lin_b,
    const float* __restrict__ out_w1, const float* __restrict__ out_b1,
    const float* __restrict__ out_w2, const float* __restrict__ out_b2,
    float* __restrict__ out) {
    extern __shared__ float sm[];
    float* sW = sm + OFF_W;
    float* sH = sm + OFF_H;
    float* sX = sm + OFF_X;
    float* sA = sm + OFF_A;
    float2* ePK = (float2*)(sm + OFF_EPK);
    int* eI = (int*)(sm + OFF_EI);
    float* sb2 = sm + OFF_B2;
    float* sbb = sm + OFF_BB;
    float* sob1 = sm + OFF_OB1;
    float* sow2 = sm + OFF_OW2;
    float* ered = sm + OFF_ERED;
    unsigned char* eJ = (unsigned char*)(sm + OFF_EJ);
    __shared__ int zz[APM];

    int mol = blockIdx.x, tid = threadIdx.x;
    int base = mol * APM;

    if (tid < APM) zz[tid] = z[base + tid];
    for (int i = tid; i < NL * F; i += 256) { sb2[i] = lin2_b[i]; sbb[i] = lin_b[i]; }
    if (tid < 50) { sob1[tid] = out_b1[tid]; sow2[tid] = out_w2[tid]; }
    // edges: precompute (t0, fr, ccut)
    {
        const float* et = (const float*)g_et + base * KNN;
        const float* ec = (const float*)g_ec + base * KNN;
        const unsigned char* ej = (const unsigned char*)g_ej + base * KNN;
        for (int i = tid; i < APM * KNN; i += 256) {
            float tpos = et[i];
            int t0 = min((int)tpos, TBL - 1);
            eI[i] = t0;
            ePK[i] = make_float2(tpos - (float)t0, ec[i]);
            eJ[i] = ej[i];
        }
    }
    __syncthreads();
    for (int i = tid; i < APM * F; i += 256) {
        int a = i / F, f = i - a * F;
        sH[i] = emb[zz[a] * F + f];
    }
    copy_w_sync(sW, lin1_w, F * F, tid);
    __syncthreads();

    for (int l = 0; l < NL; l++) {
        // x1 = h @ lin1
        gemm_tile(sH, sW, sX, nullptr, 0, tid);
        __syncthreads();
        // overlap: async-load lin2 while doing edge aggregation
        for (int i = tid * 4; i < F * F; i += 1024)
            cp_async16(sW + i, lin2_w + l * F * F + i);
        asm volatile("cp.async.commit_group;");
        // edge aggregation: agg[a,fid] = sum_s x1[j]*lerp(table)*ccut
        {
            const float2* tb = &g_tab2[l][0][0];
            int grp = tid >> 7;
            int fid = tid & 127;
            if (fid < F) {
                for (int a = grp; a < APM; a += 2) {
                    float acc = 0.f;
#pragma unroll 4
                    for (int s = 0; s < KNN; s++) {
                        int e = a * KNN + s;
                        int t0 = eI[e];
                        float2 fc = ePK[e];
                        float2 vd = tb[t0 * F + fid];
                        float w = fmaf(fc.x, vd.y, vd.x);
                        acc = fmaf(sX[(int)eJ[e] * F + fid] * w, fc.y, acc);
                    }
                    sA[a * F + fid] = acc;
                }
            }
        }
        asm volatile("cp.async.wait_group 0;" ::: "memory");
        __syncthreads();
        // t = ssp(agg @ lin2 + b2)
        gemm_tile(sA, sW, sX, sb2 + l * F, 1, tid);
        __syncthreads();
        copy_w_sync(sW, lin_w + l * F * F, F * F, tid);
        __syncthreads();
        // h += t @ lin + b
        gemm_tile(sX, sW, sH, sbb + l * F, 2, tid);
        __syncthreads();
        if (l < NL - 1) {
            copy_w_sync(sW, lin1_w + (l + 1) * F * F, F * F, tid);
        } else {
            for (int i = tid; i < F * 50; i += 256) sW[i] = out_w1[i];
        }
        __syncthreads();
    }

    // readout: e_atom = sum_j ssp(h·w1[:,j] + b1[j]) * w2[j] + b2
    {
        int a = tid & 31, q = tid >> 5;   // q in 0..7
        float e = 0.f;
        for (int j = q; j < 50; j += 8) {
            float acc = sob1[j];
#pragma unroll 4
            for (int k = 0; k < F; k++) acc = fmaf(sH[a * F + k], sW[k * 50 + j], acc);
            e += sspf(acc) * sow2[j];
        }
        ered[q * 32 + a] = e;
        __syncthreads();
        if (tid < 32) {
            float tot = out_b2[0];
#pragma unroll
            for (int q2 = 0; q2 < 8; q2++) tot += ered[q2 * 32 + tid];
            for (int off = 16; off > 0; off >>= 1)
                tot += __shfl_down_sync(0xffffffffu, tot, off);
            if (tid == 0) out[mol] = tot;
        }
    }
}

// ---------------- launch ----------------
extern "C" void kernel_launch(void* const* d_in, const int* in_sizes, int n_in,
                              void* d_out, int out_size) {
    const int* z        = (const int*)d_in[0];
    const float* pos    = (const float*)d_in[1];
    const float* emb    = (const float*)d_in[3];
    const float* mlp_w1 = (const float*)d_in[4];
    const float* mlp_b1 = (const float*)d_in[5];
    const float* mlp_w2 = (const float*)d_in[6];
    const float* mlp_b2 = (const float*)d_in[7];
    const float* lin1_w = (const float*)d_in[8];
    const float* lin2_w = (const float*)d_in[9];
    const float* lin2_b = (const float*)d_in[10];
    const float* lin_w  = (const float*)d_in[11];
    const float* lin_b  = (const float*)d_in[12];
    const float* out_w1 = (const float*)d_in[13];
    const float* out_b1 = (const float*)d_in[14];
    const float* out_w2 = (const float*)d_in[15];
    const float* out_b2 = (const float*)d_in[16];
    float* out = (float*)d_out;

    const int TBL_SMEM = (NG * F + F * F + APM * F + APM * NG + 2 * F) * 4;  // 66800

    cudaFuncSetAttribute(table_kernel, cudaFuncAttributeMaxDynamicSharedMemorySize, TBL_SMEM);
    cudaFuncSetAttribute(mol_kernel, cudaFuncAttributeMaxDynamicSharedMemorySize, MOL_SMEM_BYTES);

    knn_kernel<<<NMOL, APM>>>(pos);
    table_kernel<<<NL * NCH, 256, TBL_SMEM>>>(mlp_w1, mlp_b1, mlp_w2, mlp_b2);
    tab2_kernel<<<(NL * (TBL + 1) * F + 255) / 256, 256>>>();
    mol_kernel<<<NMOL, 256, MOL_SMEM_BYTES>>>(z, emb, lin1_w, lin2_w, lin2_b,
                                              lin_w, lin_b, out_w1, out_b1,
                                              out_w2, out_b2, out);
}

// round 5
// speedup vs baseline: 1.3812x; 1.0931x over previous
#include <cuda_runtime.h>
#include <cuda_fp16.h>
#include <math.h>

#define NATOMS 8192
#define APM 32
#define NMOL 256
#define F 100
#define NG 25
#define KNN 28
#define NL 4
#define TBL 2048
#define CUTF 6.0f
#define NCH ((TBL + 1 + 31) / 32)

// ---------------- device scratch ----------------
__device__ float   g_table[NL][TBL + 1][F];
__device__ __half2 g_tabh[NL][TBL + 1][F];      // (value, delta) fp16
__device__ unsigned char g_ej[NATOMS][KNN];
__device__ float g_et[NATOMS][KNN];
__device__ float g_ec[NATOMS][KNN];

__device__ __forceinline__ float sspf(float x) {
    float sp = (x > 0.f) ? (x + log1pf(expf(-x))) : log1pf(expf(x));
    return sp - 0.69314718055994531f;
}

__device__ __forceinline__ void ffma2(unsigned long long& d,
                                      unsigned long long a, unsigned long long b) {
    asm("fma.rn.f32x2 %0, %1, %2, %0;" : "+l"(d) : "l"(a), "l"(b));
}
__device__ __forceinline__ unsigned long long bcast2(float x) {
    unsigned long long r;
    unsigned u = __float_as_uint(x);
    asm("mov.b64 %0, {%1, %1};" : "=l"(r) : "r"(u));
    return r;
}

// ---------------- KNN (padded) ----------------
__global__ void knn_kernel(const float* __restrict__ pos) {
    int mol = blockIdx.x, a = threadIdx.x;
    int gi = mol * APM + a;
    __shared__ float px[APM], py[APM], pz[APM];
    px[a] = pos[gi * 3 + 0]; py[a] = pos[gi * 3 + 1]; pz[a] = pos[gi * 3 + 2];
    __syncthreads();
    float d[APM];
    float ax = px[a], ay = py[a], az = pz[a];
    for (int j = 0; j < APM; j++) {
        float dx = ax - px[j], dy = ay - py[j], dz = az - pz[j];
        float d2 = dx * dx + dy * dy + dz * dz;
        d[j] = (j == a || d2 > CUTF * CUTF) ? 1e30f : sqrtf(d2);
    }
    for (int s = 0; s < KNN; s++) {
        float best = 1e29f; int bj = -1;
        for (int j = 0; j < APM; j++)
            if (d[j] < best) { best = d[j]; bj = j; }
        if (bj >= 0) {
            g_ej[gi][s] = (unsigned char)bj;
            g_et[gi][s] = best * ((float)TBL / CUTF);
            g_ec[gi][s] = 0.5f * (cosf(best * (3.14159265358979323846f / CUTF)) + 1.0f);
            d[bj] = 1e30f;
        } else {
            g_ej[gi][s] = 0; g_et[gi][s] = 0.f; g_ec[gi][s] = 0.f;
        }
    }
}

// ---------------- filter table ----------------
__global__ void table_kernel(const float* __restrict__ mlp_w1, const float* __restrict__ mlp_b1,
                             const float* __restrict__ mlp_w2, const float* __restrict__ mlp_b2) {
    extern __shared__ float sm[];
    float* w1 = sm;
    float* w2 = w1 + NG * F;
    float* shid = w2 + F * F;
    float* sea = shid + APM * F;
    float* b1 = sea + APM * NG;
    float* b2 = b1 + F;

    int l = blockIdx.x / NCH;
    int c = blockIdx.x % NCH;
    int tid = threadIdx.x;

    for (int i = tid; i < NG * F; i += blockDim.x) w1[i] = mlp_w1[l * NG * F + i];
    for (int i = tid; i < F * F; i += blockDim.x) w2[i] = mlp_w2[l * F * F + i];
    if (tid < F) { b1[tid] = mlp_b1[l * F + tid]; b2[tid] = mlp_b2[l * F + tid]; }
    __syncthreads();

    for (int idx = tid; idx < APM * NG; idx += blockDim.x) {
        int tl = idx / NG, g = idx % NG;
        int t = c * 32 + tl;
        float dd = (float)t * (CUTF / (float)TBL);
        float u = dd - 0.25f * (float)g;
        sea[idx] = expf(-8.0f * u * u);
    }
    __syncthreads();

    if (tid < 200) {
        int ta = tid / 25, fa = tid % 25;
        float acc[4][4];
#pragma unroll
        for (int r = 0; r < 4; r++)
#pragma unroll
            for (int q = 0; q < 4; q++) acc[r][q] = b1[fa * 4 + q];
#pragma unroll
        for (int k = 0; k < NG; k++) {
            float4 wv = *(const float4*)&w1[k * F + fa * 4];
#pragma unroll
            for (int r = 0; r < 4; r++) {
                float av = sea[(ta * 4 + r) * NG + k];
                acc[r][0] += av * wv.x; acc[r][1] += av * wv.y;
                acc[r][2] += av * wv.z; acc[r][3] += av * wv.w;
            }
        }
#pragma unroll
        for (int r = 0; r < 4; r++)
#pragma unroll
            for (int q = 0; q < 4; q++)
                shid[(ta * 4 + r) * F + fa * 4 + q] = sspf(acc[r][q]);
    }
    __syncthreads();

    if (tid < 200) {
        int ta = tid / 25, fa = tid % 25;
        float acc[4][4];
#pragma unroll
        for (int r = 0; r < 4; r++)
#pragma unroll
            for (int q = 0; q < 4; q++) acc[r][q] = b2[fa * 4 + q];
#pragma unroll 4
        for (int k = 0; k < F; k++) {
            float4 wv = *(const float4*)&w2[k * F + fa * 4];
#pragma unroll
            for (int r = 0; r < 4; r++) {
                float av = shid[(ta * 4 + r) * F + k];
                acc[r][0] += av * wv.x; acc[r][1] += av * wv.y;
                acc[r][2] += av * wv.z; acc[r][3] += av * wv.w;
            }
        }
#pragma unroll
        for (int r = 0; r < 4; r++) {
            int t = c * 32 + ta * 4 + r;
            if (t <= TBL) {
#pragma unroll
                for (int q = 0; q < 4; q++)
                    g_table[l][t][fa * 4 + q] = acc[r][q];
            }
        }
    }
}

// ---------------- float table -> half2 (v, dv) ----------------
__global__ void tabh_kernel() {
    const int PER_L = (TBL + 1) * F;
    int idx = blockIdx.x * blockDim.x + threadIdx.x;
    if (idx >= NL * PER_L) return;
    int j = idx % PER_L;
    int t = j / F;
    const float* base = &g_table[0][0][0];
    float v = base[idx];
    float nv = (t < TBL) ? base[idx + F] : v;
    __half2* out = &g_tabh[0][0][0];
    out[idx] = __floats2half2_rn(v, nv - v);
}

// ---------------- fused mol kernel: smem layout (float offsets) ----------------
#define OFF_W 0          // 10000
#define OFF_H 10000      // 3200
#define OFF_X 13200      // 3200   (also readout padded copy: 3232 <= 6400 span w/ sA)
#define OFF_A 16400      // 3200
#define OFF_P 19600      // 3200
#define OFF_EPK 22800    // float2[896] (fr, ccut) = 1792
#define OFF_EO 24592     // int[896] table row offset t0*F
#define OFF_B2 25488     // 400
#define OFF_BB 25888     // 400
#define OFF_OB1 26288    // 64
#define OFF_OW2 26352    // 64
#define OFF_ERED 26416   // 512
#define OFF_EJ 26928     // 896 bytes = 224 floats
#define MOL_SMEM_FLOATS (26928 + 224)
#define MOL_SMEM_BYTES (MOL_SMEM_FLOATS * 4)

__device__ __forceinline__ void cp_async16(float* smem_dst, const float* gsrc) {
    unsigned sa = (unsigned)__cvta_generic_to_shared(smem_dst);
    asm volatile("cp.async.ca.shared.global [%0], [%1], 16;" :: "r"(sa), "l"(gsrc));
}

// K-split GEMM: team0 (threads 0..199) k=[0,50) -> P0, team1 (256..455) k=[50,100) -> P1
__device__ __forceinline__ void gemm_split(const float* __restrict__ A,
                                           const float* __restrict__ W,
                                           float* __restrict__ P0,
                                           float* __restrict__ P1, int tid) {
    int team = tid >> 8;
    int local = tid & 255;
    if (local >= 200) return;
    float* P = team ? P1 : P0;
    int kb = team * 50;
    int ta = local / 25, fa = local - (local / 25) * 25;
    unsigned long long acc[4][2];
#pragma unroll
    for (int r = 0; r < 4; r++) { acc[r][0] = 0ull; acc[r][1] = 0ull; }
#pragma unroll 5
    for (int kk = 0; kk < 50; kk++) {
        int k = kb + kk;
        ulonglong2 wv = *(const ulonglong2*)&W[k * F + fa * 4];
#pragma unroll
        for (int r = 0; r < 4; r++) {
            unsigned long long av = bcast2(A[(ta * 4 + r) * F + k]);
            ffma2(acc[r][0], av, wv.x);
            ffma2(acc[r][1], av, wv.y);
        }
    }
#pragma unroll
    for (int r = 0; r < 4; r++)
        *(ulonglong2*)&P[(ta * 4 + r) * F + fa * 4] = make_ulonglong2(acc[r][0], acc[r][1]);
}

__global__ __launch_bounds__(512, 2) void mol_kernel(
    const int* __restrict__ z, const float* __restrict__ emb,
    const float* __restrict__ lin1_w, const float* __restrict__ lin2_w,
    const float* __restrict__ lin2_b, const float* __restrict__ lin_w,
    const float* __restrict__ lin_b,
    const float* __restrict__ out_w1, const float* __restrict__ out_b1,
    const float* __restrict__ out_w2, const float* __restrict__ out_b2,
    float* __restrict__ out) {
    extern __shared__ float sm[];
    float* sW = sm + OFF_W;
    float* sH = sm + OFF_H;
    float* sX = sm + OFF_X;
    float* sA = sm + OFF_A;
    float* sP = sm + OFF_P;
    float2* ePK = (float2*)(sm + OFF_EPK);
    int* eO = (int*)(sm + OFF_EO);
    float* sb2 = sm + OFF_B2;
    float* sbb = sm + OFF_BB;
    float* sob1 = sm + OFF_OB1;
    float* sow2 = sm + OFF_OW2;
    float* ered = sm + OFF_ERED;
    unsigned char* eJ = (unsigned char*)(sm + OFF_EJ);
    __shared__ int zz[APM];

    int mol = blockIdx.x, tid = threadIdx.x;
    int base = mol * APM;

    if (tid < APM) zz[tid] = z[base + tid];
    for (int i = tid; i < NL * F; i += 512) { sb2[i] = lin2_b[i]; sbb[i] = lin_b[i]; }
    if (tid < 50) { sob1[tid] = out_b1[tid]; sow2[tid] = out_w2[tid]; }
    {
        const float* et = (const float*)g_et + base * KNN;
        const float* ec = (const float*)g_ec + base * KNN;
        const unsigned char* ej = (const unsigned char*)g_ej + base * KNN;
        for (int i = tid; i < APM * KNN; i += 512) {
            float tpos = et[i];
            int t0 = min((int)tpos, TBL - 1);
            eO[i] = t0 * F;
            ePK[i] = make_float2(tpos - (float)t0, ec[i]);
            eJ[i] = ej[i];
        }
    }
    for (int i = tid * 4; i < F * F; i += 2048)
        cp_async16(sW + i, lin1_w + i);
    asm volatile("cp.async.commit_group;");
    __syncthreads();
    for (int i = tid; i < APM * F; i += 512) {
        int a = i / F, f = i - a * F;
        sH[i] = emb[zz[a] * F + f];
    }
    asm volatile("cp.async.wait_group 0;" ::: "memory");
    __syncthreads();

    for (int l = 0; l < NL; l++) {
        // ---- x1 = h @ lin1 (K-split partials) ----
        gemm_split(sH, sW, sX, sP, tid);
        __syncthreads();
        // epilogue: x1 = p0+p1 ; concurrently prefetch lin2
        for (int i = tid * 4; i < F * F; i += 2048)
            cp_async16(sW + i, lin2_w + l * F * F + i);
        asm volatile("cp.async.commit_group;");
        for (int i = tid * 4; i < APM * F; i += 2048) {
            float4 a0 = *(float4*)&sX[i];
            float4 b0 = *(float4*)&sP[i];
            a0.x += b0.x; a0.y += b0.y; a0.z += b0.z; a0.w += b0.w;
            *(float4*)&sX[i] = a0;
        }
        __syncthreads();
        // ---- edge aggregation ----
        {
            const __half2* tb = &g_tabh[l][0][0];
            int grp = tid >> 7;
            int fid = tid & 127;
            if (fid < F) {
                for (int a = grp; a < APM; a += 4) {
                    float acc = 0.f;
#pragma unroll 7
                    for (int s = 0; s < KNN; s++) {
                        int e = a * KNN + s;
                        int off = eO[e];
                        float2 fc = ePK[e];
                        float2 vd = __half22float2(tb[off + fid]);
                        float w = fmaf(fc.x, vd.y, vd.x);
                        acc = fmaf(sX[(int)eJ[e] * F + fid] * w, fc.y, acc);
                    }
                    sA[a * F + fid] = acc;
                }
            }
        }
        asm volatile("cp.async.wait_group 0;" ::: "memory");
        __syncthreads();
        // ---- t = ssp(agg @ lin2 + b2) ----
        gemm_split(sA, sW, sX, sP, tid);
        __syncthreads();
        for (int i = tid * 4; i < APM * F; i += 2048) {
            int f = i - (i / F) * F;
            float4 a0 = *(float4*)&sX[i];
            float4 b0 = *(float4*)&sP[i];
            float4 bi = *(float4*)&sb2[l * F + f];
            a0.x = sspf(a0.x + b0.x + bi.x);
            a0.y = sspf(a0.y + b0.y + bi.y);
            a0.z = sspf(a0.z + b0.z + bi.z);
            a0.w = sspf(a0.w + b0.w + bi.w);
            *(float4*)&sX[i] = a0;
        }
        __syncthreads();
        for (int i = tid * 4; i < F * F; i += 2048)
            cp_async16(sW + i, lin_w + l * F * F + i);
        asm volatile("cp.async.commit_group;");
        asm volatile("cp.async.wait_group 0;" ::: "memory");
        __syncthreads();
        // ---- h += t @ lin + b ----
        gemm_split(sX, sW, sA, sP, tid);
        __syncthreads();
        for (int i = tid * 4; i < APM * F; i += 2048) {
            int f = i - (i / F) * F;
            float4 h0 = *(float4*)&sH[i];
            float4 a0 = *(float4*)&sA[i];
            float4 b0 = *(float4*)&sP[i];
            float4 bi = *(float4*)&sbb[l * F + f];
            h0.x += a0.x + b0.x + bi.x;
            h0.y += a0.y + b0.y + bi.y;
            h0.z += a0.z + b0.z + bi.z;
            h0.w += a0.w + b0.w + bi.w;
            *(float4*)&sH[i] = h0;
        }
        __syncthreads();
        if (l < NL - 1) {
            for (int i = tid * 4; i < F * F; i += 2048)
                cp_async16(sW + i, lin1_w + (l + 1) * F * F + i);
        } else {
            for (int i = tid * 4; i < F * 50; i += 2048)
                cp_async16(sW + i, out_w1 + i);
        }
        asm volatile("cp.async.commit_group;");
        asm volatile("cp.async.wait_group 0;" ::: "memory");
        __syncthreads();
    }

    // readout: copy h into stride-101 buffer (conflict-free), then reduce
    float* sR = sX;   // 32*101 = 3232 floats, fits in sX..sA span
    for (int i = tid; i < APM * F; i += 512) {
        int a = i / F, k = i - a * F;
        sR[a * 101 + k] = sH[i];
    }
    __syncthreads();
    {
        int a = tid & 31, q = tid >> 5;  // q 0..15
        float e = 0.f;
        for (int j = q; j < 50; j += 16) {
            float acc = sob1[j];
#pragma unroll 4
            for (int k = 0; k < F; k++) acc = fmaf(sR[a * 101 + k], sW[k * 50 + j], acc);
            e += sspf(acc) * sow2[j];
        }
        ered[q * 32 + a] = e;
        __syncthreads();
        if (tid < 32) {
            float tot = out_b2[0];
#pragma unroll
            for (int q2 = 0; q2 < 16; q2++) tot += ered[q2 * 32 + tid];
            for (int off = 16; off > 0; off >>= 1)
                tot += __shfl_down_sync(0xffffffffu, tot, off);
            if (tid == 0) out[mol] = tot;
        }
    }
}

// ---------------- launch ----------------
extern "C" void kernel_launch(void* const* d_in, const int* in_sizes, int n_in,
                              void* d_out, int out_size) {
    const int* z        = (const int*)d_in[0];
    const float* pos    = (const float*)d_in[1];
    const float* emb    = (const float*)d_in[3];
    const float* mlp_w1 = (const float*)d_in[4];
    const float* mlp_b1 = (const float*)d_in[5];
    const float* mlp_w2 = (const float*)d_in[6];
    const float* mlp_b2 = (const float*)d_in[7];
    const float* lin1_w = (const float*)d_in[8];
    const float* lin2_w = (const float*)d_in[9];
    const float* lin2_b = (const float*)d_in[10];
    const float* lin_w  = (const float*)d_in[11];
    const float* lin_b  = (const float*)d_in[12];
    const float* out_w1 = (const float*)d_in[13];
    const float* out_b1 = (const float*)d_in[14];
    const float* out_w2 = (const float*)d_in[15];
    const float* out_b2 = (const float*)d_in[16];
    float* out = (float*)d_out;

    const int TBL_SMEM = (NG * F + F * F + APM * F + APM * NG + 2 * F) * 4;

    cudaFuncSetAttribute(table_kernel, cudaFuncAttributeMaxDynamicSharedMemorySize, TBL_SMEM);
    cudaFuncSetAttribute(mol_kernel, cudaFuncAttributeMaxDynamicSharedMemorySize, MOL_SMEM_BYTES);

    knn_kernel<<<NMOL, APM>>>(pos);
    table_kernel<<<NL * NCH, 256, TBL_SMEM>>>(mlp_w1, mlp_b1, mlp_w2, mlp_b2);
    tabh_kernel<<<(NL * (TBL + 1) * F + 255) / 256, 256>>>();
    mol_kernel<<<NMOL, 512, MOL_SMEM_BYTES>>>(z, emb, lin1_w, lin2_w, lin2_b,
                                              lin_w, lin_b, out_w1, out_b1,
                                              out_w2, out_b2, out);
}

// round 6
// speedup vs baseline: 1.5724x; 1.1385x over previous
#include <cuda_runtime.h>
#include <cuda_fp16.h>
#include <math.h>

#define NATOMS 8192
#define APM 32
#define NMOL 256
#define F 100
#define NG 25
#define KNN 28
#define NL 4
#define TBL 1024
#define CUTF 6.0f
#define NCH ((TBL + 1 + 31) / 32)
#define TPAD 128   // padded table row (half2 elements)
#define XLD 128    // padded x1 stride (floats)

// ---------------- device scratch ----------------
__device__ float   g_table[NL][TBL + 1][F];
__device__ __half2 g_tabh[NL][TBL + 1][TPAD];   // (value, delta) fp16, padded rows
__device__ unsigned char g_ej[NATOMS][KNN];
__device__ float g_et[NATOMS][KNN];
__device__ float g_ec[NATOMS][KNN];

__device__ __forceinline__ float sspf(float x) {
    float sp = (x > 0.f) ? (x + log1pf(expf(-x))) : log1pf(expf(x));
    return sp - 0.69314718055994531f;
}

__device__ __forceinline__ void ffma2(unsigned long long& d,
                                      unsigned long long a, unsigned long long b) {
    asm("fma.rn.f32x2 %0, %1, %2, %0;" : "+l"(d) : "l"(a), "l"(b));
}
__device__ __forceinline__ unsigned long long bcast2(float x) {
    unsigned long long r;
    unsigned u = __float_as_uint(x);
    asm("mov.b64 %0, {%1, %1};" : "=l"(r) : "r"(u));
    return r;
}

// ---------------- KNN (padded) ----------------
__global__ void knn_kernel(const float* __restrict__ pos) {
    int mol = blockIdx.x, a = threadIdx.x;
    int gi = mol * APM + a;
    __shared__ float px[APM], py[APM], pz[APM];
    px[a] = pos[gi * 3 + 0]; py[a] = pos[gi * 3 + 1]; pz[a] = pos[gi * 3 + 2];
    __syncthreads();
    float d[APM];
    float ax = px[a], ay = py[a], az = pz[a];
    for (int j = 0; j < APM; j++) {
        float dx = ax - px[j], dy = ay - py[j], dz = az - pz[j];
        float d2 = dx * dx + dy * dy + dz * dz;
        d[j] = (j == a || d2 > CUTF * CUTF) ? 1e30f : sqrtf(d2);
    }
    for (int s = 0; s < KNN; s++) {
        float best = 1e29f; int bj = -1;
        for (int j = 0; j < APM; j++)
            if (d[j] < best) { best = d[j]; bj = j; }
        if (bj >= 0) {
            g_ej[gi][s] = (unsigned char)bj;
            g_et[gi][s] = best * ((float)TBL / CUTF);
            g_ec[gi][s] = 0.5f * (cosf(best * (3.14159265358979323846f / CUTF)) + 1.0f);
            d[bj] = 1e30f;
        } else {
            g_ej[gi][s] = 0; g_et[gi][s] = 0.f; g_ec[gi][s] = 0.f;
        }
    }
}

// ---------------- filter table ----------------
__global__ void table_kernel(const float* __restrict__ mlp_w1, const float* __restrict__ mlp_b1,
                             const float* __restrict__ mlp_w2, const float* __restrict__ mlp_b2) {
    extern __shared__ float sm[];
    float* w1 = sm;
    float* w2 = w1 + NG * F;
    float* shid = w2 + F * F;
    float* sea = shid + APM * F;
    float* b1 = sea + APM * NG;
    float* b2 = b1 + F;

    int l = blockIdx.x / NCH;
    int c = blockIdx.x % NCH;
    int tid = threadIdx.x;

    for (int i = tid; i < NG * F; i += blockDim.x) w1[i] = mlp_w1[l * NG * F + i];
    for (int i = tid; i < F * F; i += blockDim.x) w2[i] = mlp_w2[l * F * F + i];
    if (tid < F) { b1[tid] = mlp_b1[l * F + tid]; b2[tid] = mlp_b2[l * F + tid]; }
    __syncthreads();

    for (int idx = tid; idx < APM * NG; idx += blockDim.x) {
        int tl = idx / NG, g = idx % NG;
        int t = c * 32 + tl;
        float dd = (float)t * (CUTF / (float)TBL);
        float u = dd - 0.25f * (float)g;
        sea[idx] = expf(-8.0f * u * u);
    }
    __syncthreads();

    if (tid < 200) {
        int ta = tid / 25, fa = tid % 25;
        float acc[4][4];
#pragma unroll
        for (int r = 0; r < 4; r++)
#pragma unroll
            for (int q = 0; q < 4; q++) acc[r][q] = b1[fa * 4 + q];
#pragma unroll
        for (int k = 0; k < NG; k++) {
            float4 wv = *(const float4*)&w1[k * F + fa * 4];
#pragma unroll
            for (int r = 0; r < 4; r++) {
                float av = sea[(ta * 4 + r) * NG + k];
                acc[r][0] += av * wv.x; acc[r][1] += av * wv.y;
                acc[r][2] += av * wv.z; acc[r][3] += av * wv.w;
            }
        }
#pragma unroll
        for (int r = 0; r < 4; r++)
#pragma unroll
            for (int q = 0; q < 4; q++)
                shid[(ta * 4 + r) * F + fa * 4 + q] = sspf(acc[r][q]);
    }
    __syncthreads();

    if (tid < 200) {
        int ta = tid / 25, fa = tid % 25;
        float acc[4][4];
#pragma unroll
        for (int r = 0; r < 4; r++)
#pragma unroll
            for (int q = 0; q < 4; q++) acc[r][q] = b2[fa * 4 + q];
#pragma unroll 4
        for (int k = 0; k < F; k++) {
            float4 wv = *(const float4*)&w2[k * F + fa * 4];
#pragma unroll
            for (int r = 0; r < 4; r++) {
                float av = shid[(ta * 4 + r) * F + k];
                acc[r][0] += av * wv.x; acc[r][1] += av * wv.y;
                acc[r][2] += av * wv.z; acc[r][3] += av * wv.w;
            }
        }
#pragma unroll
        for (int r = 0; r < 4; r++) {
            int t = c * 32 + ta * 4 + r;
            if (t <= TBL) {
#pragma unroll
                for (int q = 0; q < 4; q++)
                    g_table[l][t][fa * 4 + q] = acc[r][q];
            }
        }
    }
}

// ---------------- float table -> padded half2 (v, dv) ----------------
__global__ void tabh_kernel() {
    const int PER_L = (TBL + 1) * F;
    int idx = blockIdx.x * blockDim.x + threadIdx.x;
    if (idx >= NL * PER_L) return;
    int l = idx / PER_L;
    int j = idx - l * PER_L;
    int t = j / F;
    int f = j - t * F;
    float v = g_table[l][t][f];
    float nv = (t < TBL) ? g_table[l][t + 1][f] : v;
    g_tabh[l][t][f] = __floats2half2_rn(v, nv - v);
}

// ---------------- fused mol kernel smem layout (float offsets) ----------------
#define OFF_W 0          // 10000
#define OFF_H 10000      // 3200 (stride 100)
#define OFF_X 13200      // 4096 (stride 128)
#define OFF_A 17296      // 3200
#define OFF_P 20496      // 3200
#define OFF_EM 23696     // float4[896] = 3584
#define OFF_B2 27280     // 400
#define OFF_BB 27680     // 400
#define OFF_OB1 28080    // 64
#define OFF_OW2 28144    // 64
#define MOL_SMEM_FLOATS 28208
#define MOL_SMEM_BYTES (MOL_SMEM_FLOATS * 4)

__device__ __forceinline__ void cp_async16(float* smem_dst, const float* gsrc) {
    unsigned sa = (unsigned)__cvta_generic_to_shared(smem_dst);
    asm volatile("cp.async.ca.shared.global [%0], [%1], 16;" :: "r"(sa), "l"(gsrc));
}

// K-split GEMM, A cached in float4 per 4 k-steps.
// team0 (tid<256, local<200): kb 0..11 -> C0; team1: kb 12..24 -> C1 (sP, stride F)
__device__ __forceinline__ void gemm_split(const float* __restrict__ A, int lda,
                                           const float* __restrict__ W,
                                           float* __restrict__ C0, int ldc0,
                                           float* __restrict__ C1, int tid) {
    int team = tid >> 8;
    int local = tid & 255;
    if (local >= 200) return;
    int ta = local / 25, fa = local - (local / 25) * 25;
    float* C = team ? C1 : C0;
    int ldc = team ? F : ldc0;
    int kb_lo = team ? 12 : 0;
    int kb_hi = team ? 25 : 12;
    const int lda4 = lda >> 2;
    const float4* A4 = (const float4*)A;
    unsigned long long acc[4][2];
#pragma unroll
    for (int r = 0; r < 4; r++) { acc[r][0] = 0ull; acc[r][1] = 0ull; }
#pragma unroll 2
    for (int kb = kb_lo; kb < kb_hi; kb++) {
        float ar[4][4];
#pragma unroll
        for (int r = 0; r < 4; r++)
            *(float4*)ar[r] = A4[(ta * 4 + r) * lda4 + kb];
#pragma unroll
        for (int kk = 0; kk < 4; kk++) {
            int k = kb * 4 + kk;
            ulonglong2 wv = *(const ulonglong2*)&W[k * F + fa * 4];
#pragma unroll
            for (int r = 0; r < 4; r++) {
                unsigned long long av = bcast2(ar[r][kk]);
                ffma2(acc[r][0], av, wv.x);
                ffma2(acc[r][1], av, wv.y);
            }
        }
    }
#pragma unroll
    for (int r = 0; r < 4; r++)
        *(ulonglong2*)&C[(ta * 4 + r) * ldc + fa * 4] = make_ulonglong2(acc[r][0], acc[r][1]);
}

__global__ __launch_bounds__(512, 2) void mol_kernel(
    const int* __restrict__ z, const float* __restrict__ emb,
    const float* __restrict__ lin1_w, const float* __restrict__ lin2_w,
    const float* __restrict__ lin2_b, const float* __restrict__ lin_w,
    const float* __restrict__ lin_b,
    const float* __restrict__ out_w1, const float* __restrict__ out_b1,
    const float* __restrict__ out_w2, const float* __restrict__ out_b2,
    float* __restrict__ out) {
    extern __shared__ float sm[];
    float* sW = sm + OFF_W;
    float* sH = sm + OFF_H;
    float* sX = sm + OFF_X;     // stride XLD=128
    float* sA = sm + OFF_A;
    float* sP = sm + OFF_P;
    float4* eM = (float4*)(sm + OFF_EM);
    float* sb2 = sm + OFF_B2;
    float* sbb = sm + OFF_BB;
    float* sob1 = sm + OFF_OB1;
    float* sow2 = sm + OFF_OW2;
    __shared__ int zz[APM];

    int mol = blockIdx.x, tid = threadIdx.x;
    int base = mol * APM;

    if (tid < APM) zz[tid] = z[base + tid];
    for (int i = tid; i < NL * F; i += 512) { sb2[i] = lin2_b[i]; sbb[i] = lin_b[i]; }
    if (tid < 50) { sob1[tid] = out_b1[tid]; sow2[tid] = out_w2[tid]; }
    {
        const float* et = (const float*)g_et + base * KNN;
        const float* ec = (const float*)g_ec + base * KNN;
        const unsigned char* ej = (const unsigned char*)g_ej + base * KNN;
        for (int i = tid; i < APM * KNN; i += 512) {
            float tpos = et[i];
            int t0 = min((int)tpos, TBL - 1);
            eM[i] = make_float4(__int_as_float(t0 * TPAD),
                                __int_as_float((int)ej[i] * XLD),
                                tpos - (float)t0, ec[i]);
        }
    }
    for (int i = tid * 4; i < F * F; i += 2048)
        cp_async16(sW + i, lin1_w + i);
    asm volatile("cp.async.commit_group;");
    __syncthreads();
    for (int i = tid; i < APM * F; i += 512) {
        int a = i / F, f = i - a * F;
        sH[i] = emb[zz[a] * F + f];
    }
    asm volatile("cp.async.wait_group 0;" ::: "memory");
    __syncthreads();

    for (int l = 0; l < NL; l++) {
        // ---- x1 = h @ lin1 : partials in sX (128-stride) and sP ----
        gemm_split(sH, F, sW, sX, XLD, sP, tid);
        __syncthreads();
        // combine + prefetch lin2
        for (int i = tid * 4; i < F * F; i += 2048)
            cp_async16(sW + i, lin2_w + l * F * F + i);
        asm volatile("cp.async.commit_group;");
        for (int i = tid; i < APM * (F / 4); i += 512) {
            int a = i / 25, f4 = i - a * 25;
            float4 v = *(float4*)&sX[a * XLD + f4 * 4];
            float4 p = *(float4*)&sP[a * F + f4 * 4];
            v.x += p.x; v.y += p.y; v.z += p.z; v.w += p.w;
            *(float4*)&sX[a * XLD + f4 * 4] = v;
        }
        __syncthreads();
        // ---- edge aggregation -> sA ----
        {
            const __half2* tb = &g_tabh[l][0][0];
            int grp = tid >> 7;
            int fid = tid & 127;
            if (fid < F) {
                for (int a = grp; a < APM; a += 4) {
                    float acc = 0.f;
#pragma unroll 7
                    for (int s = 0; s < KNN; s++) {
                        float4 m = eM[a * KNN + s];
                        int off = __float_as_int(m.x);
                        int jof = __float_as_int(m.y);
                        float2 vd = __half22float2(tb[off + fid]);
                        float w = fmaf(m.z, vd.y, vd.x);
                        acc = fmaf(sX[jof + fid] * w, m.w, acc);
                    }
                    sA[a * F + fid] = acc;
                }
            }
        }
        asm volatile("cp.async.wait_group 0;" ::: "memory");
        __syncthreads();
        // ---- t = ssp(agg @ lin2 + b2) -> sX ----
        gemm_split(sA, F, sW, sX, XLD, sP, tid);
        __syncthreads();
        for (int i = tid; i < APM * (F / 4); i += 512) {
            int a = i / 25, f4 = i - a * 25;
            float4 v = *(float4*)&sX[a * XLD + f4 * 4];
            float4 p = *(float4*)&sP[a * F + f4 * 4];
            float4 bi = *(float4*)&sb2[l * F + f4 * 4];
            v.x = sspf(v.x + p.x + bi.x);
            v.y = sspf(v.y + p.y + bi.y);
            v.z = sspf(v.z + p.z + bi.z);
            v.w = sspf(v.w + p.w + bi.w);
            *(float4*)&sX[a * XLD + f4 * 4] = v;
        }
        __syncthreads();
        for (int i = tid * 4; i < F * F; i += 2048)
            cp_async16(sW + i, lin_w + l * F * F + i);
        asm volatile("cp.async.commit_group;");
        asm volatile("cp.async.wait_group 0;" ::: "memory");
        __syncthreads();
        // ---- h += t @ lin + b : partials sA + sP ----
        gemm_split(sX, XLD, sW, sA, F, sP, tid);
        __syncthreads();
        for (int i = tid; i < APM * (F / 4); i += 512) {
            int a = i / 25, f4 = i - a * 25;
            float4 h0 = *(float4*)&sH[a * F + f4 * 4];
            float4 a0 = *(float4*)&sA[a * F + f4 * 4];
            float4 p0 = *(float4*)&sP[a * F + f4 * 4];
            float4 bi = *(float4*)&sbb[l * F + f4 * 4];
            h0.x += a0.x + p0.x + bi.x;
            h0.y += a0.y + p0.y + bi.y;
            h0.z += a0.z + p0.z + bi.z;
            h0.w += a0.w + p0.w + bi.w;
            *(float4*)&sH[a * F + f4 * 4] = h0;
        }
        __syncthreads();
        if (l < NL - 1) {
            for (int i = tid * 4; i < F * F; i += 2048)
                cp_async16(sW + i, lin1_w + (l + 1) * F * F + i);
        } else {
            for (int i = tid * 4; i < F * 50; i += 2048)
                cp_async16(sW + i, out_w1 + i);
        }
        asm volatile("cp.async.commit_group;");
        asm volatile("cp.async.wait_group 0;" ::: "memory");
        __syncthreads();
    }

    // ---- readout (reads sH directly; ered reuses sA) ----
    {
        int a = tid & 31, q = tid >> 5;  // q 0..15
        float e = 0.f;
        for (int j = q; j < 50; j += 16) {
            float acc = sob1[j];
#pragma unroll 4
            for (int k = 0; k < F; k++) acc = fmaf(sH[a * F + k], sW[k * 50 + j], acc);
            e += sspf(acc) * sow2[j];
        }
        sA[q * 32 + a] = e;
        __syncthreads();
        if (tid < 32) {
            float tot = out_b2[0];
#pragma unroll
            for (int q2 = 0; q2 < 16; q2++) tot += sA[q2 * 32 + tid];
            for (int off = 16; off > 0; off >>= 1)
                tot += __shfl_down_sync(0xffffffffu, tot, off);
            if (tid == 0) out[mol] = tot;
        }
    }
}

// ---------------- launch ----------------
extern "C" void kernel_launch(void* const* d_in, const int* in_sizes, int n_in,
                              void* d_out, int out_size) {
    const int* z        = (const int*)d_in[0];
    const float* pos    = (const float*)d_in[1];
    const float* emb    = (const float*)d_in[3];
    const float* mlp_w1 = (const float*)d_in[4];
    const float* mlp_b1 = (const float*)d_in[5];
    const float* mlp_w2 = (const float*)d_in[6];
    const float* mlp_b2 = (const float*)d_in[7];
    const float* lin1_w = (const float*)d_in[8];
    const float* lin2_w = (const float*)d_in[9];
    const float* lin2_b = (const float*)d_in[10];
    const float* lin_w  = (const float*)d_in[11];
    const float* lin_b  = (const float*)d_in[12];
    const float* out_w1 = (const float*)d_in[13];
    const float* out_b1 = (const float*)d_in[14];
    const float* out_w2 = (const float*)d_in[15];
    const float* out_b2 = (const float*)d_in[16];
    float* out = (float*)d_out;

    const int TBL_SMEM = (NG * F + F * F + APM * F + APM * NG + 2 * F) * 4;

    cudaFuncSetAttribute(table_kernel, cudaFuncAttributeMaxDynamicSharedMemorySize, TBL_SMEM);
    cudaFuncSetAttribute(mol_kernel, cudaFuncAttributeMaxDynamicSharedMemorySize, MOL_SMEM_BYTES);

    knn_kernel<<<NMOL, APM>>>(pos);
    table_kernel<<<NL * NCH, 256, TBL_SMEM>>>(mlp_w1, mlp_b1, mlp_w2, mlp_b2);
    tabh_kernel<<<(NL * (TBL + 1) * F + 255) / 256, 256>>>();
    mol_kernel<<<NMOL, 512, MOL_SMEM_BYTES>>>(z, emb, lin1_w, lin2_w, lin2_b,
                                              lin_w, lin_b, out_w1, out_b1,
                                              out_w2, out_b2, out);
}